// round 13
// baseline (speedup 1.0000x reference)
#include <cuda_runtime.h>

// ---- block layout (one wave @ occ4: 443 <= 148*4) ----
// [0,64)    f^2 kz5 : 1 block per 256x256 image
// [64,80)   f^2 kz3 : 1 block per 4 128x128 images
// [80,301)  kz5 main: pair-col threads: 64 img x 126 pairs x 7 chunks (R=36) = 56448 thr
// [301,443) kz3 main: pair-col threads: 64 img x 63 pairs x 9 chunks (R=14) = 36288 thr
#define B5F        64
#define B3F        16
#define T5_THREADS 56448
#define B5M        221
#define T3_THREADS 36288
#define B3M        142
#define NBLOCKS    (B5F + B3F + B5M + B3M)   // 443

__device__ double g_part[NBLOCKS];
__device__ int    g_count;

typedef unsigned long long u64;

__device__ __forceinline__ u64 pack2(float lo, float hi) {
    u64 r; asm("mov.b64 %0, {%1,%2};" : "=l"(r) : "f"(lo), "f"(hi)); return r;
}
__device__ __forceinline__ u64 fma2(u64 a, u64 b, u64 c) {
    u64 d; asm("fma.rn.f32x2 %0, %1, %2, %3;" : "=l"(d) : "l"(a), "l"(b), "l"(c)); return d;
}
__device__ __forceinline__ u64 add2(u64 a, u64 b) {
    u64 d; asm("add.rn.f32x2 %0, %1, %2;" : "=l"(d) : "l"(a), "l"(b)); return d;
}
__device__ __forceinline__ u64 mul2(u64 a, u64 b) {
    u64 d; asm("mul.rn.f32x2 %0, %1, %2;" : "=l"(d) : "l"(a), "l"(b)); return d;
}
__device__ __forceinline__ void unpack2(u64 v, float& lo, float& hi) {
    asm("mov.b64 {%0,%1}, %2;" : "=f"(lo), "=f"(hi) : "l"(v));
}
__device__ __forceinline__ float lo2(u64 v){ float a,b; unpack2(v,a,b); return a; }
__device__ __forceinline__ float hi2(u64 v){ float a,b; unpack2(v,a,b); return b; }

// ---- hstats from pre-loaded raw registers ----
__device__ __forceinline__ void hstats5r(u64 A, u64 B, u64 C,
                                         u64 two2, u64 neg12, u64& o0, u64& oc)
{
    u64 pk1 = pack2(hi2(A), lo2(B));               // (f1,f2)
    u64 pk3 = pack2(hi2(B), lo2(C));               // (f3,f4)
    u64 s0 = add2(add2(A, pk1), add2(B, pk3));
    o0 = add2(s0, C);
    u64 d1 = fma2(neg12, pk1, pk3);
    u64 d2 = fma2(neg12, A, C);
    oc = fma2(two2, d2, d1);
}
__device__ __forceinline__ void hstats3r(u64 A, u64 B, u64 neg12, u64& o0, u64& oc)
{
    u64 pk1 = pack2(hi2(A), lo2(B));
    o0 = add2(add2(A, pk1), B);
    oc = fma2(neg12, A, B);
}

// ---- kz5 main: 2 cols x 36 rows, prefetch + incremental S0/Sc ----
__device__ __forceinline__ float work5(const float* __restrict__ f1, int t)
{
    if (t >= T5_THREADS) return 0.f;
    const int img   = t / 882;           // 126*7
    int rem         = t - img * 882;
    const int chunk = rem / 126;
    const int cg    = rem - chunk * 126;
    const float* __restrict__ p = f1 + (size_t)img * 65536
                                + (size_t)(chunk * 36) * 256 + cg * 2;

    const u64 two2  = pack2(2.f, 2.f);
    const u64 neg12 = pack2(-1.f, -1.f);

    u64 r0[5], rc[5];
#pragma unroll
    for (int w = 0; w < 4; w++) {
        u64 A = *reinterpret_cast<const u64*>(p);
        u64 B = *reinterpret_cast<const u64*>(p + 2);
        u64 C = *reinterpret_cast<const u64*>(p + 4);
        hstats5r(A, B, C, two2, neg12, r0[w], rc[w]);
        p += 256;
    }
    u64 S0p = add2(add2(r0[0], r0[1]), add2(r0[2], r0[3]));
    u64 Scp = add2(add2(rc[0], rc[1]), add2(rc[2], rc[3]));

    u64 A = *reinterpret_cast<const u64*>(p);
    u64 B = *reinterpret_cast<const u64*>(p + 2);
    u64 C = *reinterpret_cast<const u64*>(p + 4);
    p += 256;

    u64 accA = 0ull, accB = 0ull;
#pragma unroll
    for (int i = 0; i < 36; i++) {
        u64 nA, nB, nC;
        if (i < 35) {                     // prefetch next row
            nA = *reinterpret_cast<const u64*>(p);
            nB = *reinterpret_cast<const u64*>(p + 2);
            nC = *reinterpret_cast<const u64*>(p + 4);
            p += 256;
        }
        const int sl = (i + 4) % 5;
        hstats5r(A, B, C, two2, neg12, r0[sl], rc[sl]);

        u64 S0 = add2(S0p, r0[sl]);
        u64 Sc = add2(Scp, rc[sl]);
        const int a0 = i % 5, a1 = (i + 1) % 5, a3 = (i + 3) % 5;
        u64 d1 = fma2(neg12, r0[a1], r0[a3]);
        u64 d2 = fma2(neg12, r0[a0], r0[sl]);
        u64 Sr = fma2(two2, d2, d1);
        accA = fma2(S0, S0, accA);
        accB = fma2(Sr, Sr, accB);
        accB = fma2(Sc, Sc, accB);
        S0p = fma2(neg12, r0[a0], S0);
        Scp = fma2(neg12, rc[a0], Sc);
        A = nA; B = nB; C = nC;
    }
    float aL, aH, bL, bH;
    unpack2(accA, aL, aH); unpack2(accB, bL, bH);
    return (1.f/25.f) * (aL + aH) + (12.f/(25.f*24.f)) * (bL + bH);
}

// ---- kz3 main: 2 cols x 14 rows ----
__device__ __forceinline__ float work3(const float* __restrict__ f0, int t)
{
    const int img   = t / 567;           // 63*9
    int rem         = t - img * 567;
    const int chunk = rem / 63;
    const int cg    = rem - chunk * 63;
    const float* __restrict__ p = f0 + (size_t)img * 16384
                                + (size_t)(chunk * 14) * 128 + cg * 2;

    const u64 neg12 = pack2(-1.f, -1.f);

    u64 r0[3], rc[3];
#pragma unroll
    for (int w = 0; w < 2; w++) {
        u64 A = *reinterpret_cast<const u64*>(p);
        u64 B = *reinterpret_cast<const u64*>(p + 2);
        hstats3r(A, B, neg12, r0[w], rc[w]);
        p += 128;
    }
    u64 S0p = add2(r0[0], r0[1]);
    u64 Scp = add2(rc[0], rc[1]);

    u64 A = *reinterpret_cast<const u64*>(p);
    u64 B = *reinterpret_cast<const u64*>(p + 2);
    p += 128;

    u64 accA = 0ull, accB = 0ull;
#pragma unroll
    for (int i = 0; i < 14; i++) {
        u64 nA, nB;
        if (i < 13) {
            nA = *reinterpret_cast<const u64*>(p);
            nB = *reinterpret_cast<const u64*>(p + 2);
            p += 128;
        }
        const int sl = (i + 2) % 3, a0 = i % 3;
        hstats3r(A, B, neg12, r0[sl], rc[sl]);

        u64 S0 = add2(S0p, r0[sl]);
        u64 Sc = add2(Scp, rc[sl]);
        u64 Sr = fma2(neg12, r0[a0], r0[sl]);
        accA = fma2(S0, S0, accA);
        accB = fma2(Sr, Sr, accB);
        accB = fma2(Sc, Sc, accB);
        S0p = fma2(neg12, r0[a0], S0);
        Scp = fma2(neg12, rc[a0], Sc);
        A = nA; B = nB;
    }
    float aL, aH, bL, bH;
    unpack2(accA, aL, aH); unpack2(accB, bL, bH);
    return (1.f/9.f) * (aL + aH) + (12.f/(9.f*8.f)) * (bL + bH);
}

// ---- f^2 weighted pass, kz5: 1 block per image ----
__device__ __forceinline__ float frow5(const float* __restrict__ f1, int img, int tid)
{
    const u64* __restrict__ q = reinterpret_cast<const u64*>(f1 + (size_t)img * 65536);
    const int x0 = 2 * (tid & 127);
    const float wx0 = (float)min(min(x0 + 1, 256 - x0), 5);
    const float wx1 = (float)min(min(x0 + 2, 255 - x0), 5);
    const u64 wx2 = pack2(wx0, wx1);

    u64 acc5 = 0ull;
#pragma unroll 8
    for (int k = 2; k < 126; k++) {
        u64 F = q[tid + (k << 8)];
        acc5 = fma2(F, mul2(F, wx2), acc5);
    }
    u64 acce = 0ull;
    const int r0 = tid >> 7;
#pragma unroll
    for (int e = 0; e < 4; e++) {
        const int k = (e < 2) ? e : (124 + e);
        const int row = r0 + 2 * k;
        const float wy = (float)min(min(row + 1, 256 - row), 5);
        u64 F = q[tid + (k << 8)];
        acce = fma2(F, mul2(F, mul2(wx2, pack2(wy, wy))), acce);
    }
    float aL, aH, eL, eH;
    unpack2(acc5, aL, aH); unpack2(acce, eL, eH);
    return 5.f * (aL + aH) + (eL + eH);
}

// ---- f^2 weighted pass, kz3: per image ----
__device__ __forceinline__ float frow3img(const float* __restrict__ f0, int img, int tid)
{
    const u64* __restrict__ q = reinterpret_cast<const u64*>(f0 + (size_t)img * 16384);
    const int x0 = 2 * (tid & 63);
    const float wx0 = (float)min(min(x0 + 1, 128 - x0), 3);
    const float wx1 = (float)min(min(x0 + 2, 127 - x0), 3);
    const u64 wx2 = pack2(wx0, wx1);

    u64 acc3 = 0ull;
#pragma unroll 8
    for (int k = 1; k < 31; k++) {
        u64 F = q[tid + (k << 8)];
        acc3 = fma2(F, mul2(F, wx2), acc3);
    }
    u64 acce = 0ull;
    const int r0 = tid >> 6;
#pragma unroll
    for (int e = 0; e < 2; e++) {
        const int k = e * 31;
        const int row = r0 + 4 * k;
        const float wy = (float)min(min(row + 1, 128 - row), 3);
        u64 F = q[tid + (k << 8)];
        acce = fma2(F, mul2(F, mul2(wx2, pack2(wy, wy))), acce);
    }
    float aL, aH, eL, eH;
    unpack2(acc3, aL, aH); unpack2(acce, eL, eH);
    return 3.f * (aL + aH) + (eL + eH);
}

__global__ void __launch_bounds__(256, 4) fused_kernel(const float* __restrict__ f0,
                                                       const float* __restrict__ f1,
                                                       float* __restrict__ out)
{
    const int tid = threadIdx.x;
    const int b   = blockIdx.x;
    float acc = 0.f;
    double scale;

    const double sc5 = 1.0 / (32.0 * 252.0 * 252.0);
    const double sc3 = 1.0 / (32.0 * 126.0 * 126.0);

    if (b < B5F) {                                     // f^2 kz5 (positive)
        acc = frow5(f1, b, tid);
        scale = sc5;
    } else if (b < B5F + B3F) {                        // f^2 kz3 (positive), 4 imgs
        const int i0 = (b - B5F) * 4;
        acc = (frow3img(f0, i0, tid)     + frow3img(f0, i0 + 1, tid))
            + (frow3img(f0, i0 + 2, tid) + frow3img(f0, i0 + 3, tid));
        scale = sc3;
    } else if (b < B5F + B3F + B5M) {                  // kz5 main (negative)
        acc = work5(f1, (b - B5F - B3F) * 256 + tid);
        scale = -sc5;
    } else {                                           // kz3 main (negative)
        const int t = (b - B5F - B3F - B5M) * 256 + tid;
        if (t < T3_THREADS) acc = work3(f0, t);
        scale = -sc3;
    }

#pragma unroll
    for (int o = 16; o > 0; o >>= 1) acc += __shfl_down_sync(0xffffffffu, acc, o);
    __shared__ float wsum[8];
    __shared__ bool  lastflag;
    if ((tid & 31) == 0) wsum[tid >> 5] = acc;
    __syncthreads();
    if (tid < 32) {
        float v = (tid < 8) ? wsum[tid] : 0.f;
#pragma unroll
        for (int o = 4; o > 0; o >>= 1) v += __shfl_down_sync(0xffffffffu, v, o);
        if (tid == 0) {
            g_part[b] = (double)v * scale;
            __threadfence();
            int done = atomicAdd(&g_count, 1);
            lastflag = (done == NBLOCKS - 1);
        }
    }
    __syncthreads();

    if (lastflag) {
        __threadfence();
        double s = 0.0;
        for (int i = tid; i < NBLOCKS; i += 256) s += g_part[i];
#pragma unroll
        for (int o = 16; o > 0; o >>= 1) s += __shfl_down_sync(0xffffffffu, s, o);
        __shared__ double ws[8];
        if ((tid & 31) == 0) ws[tid >> 5] = s;
        __syncthreads();
        if (tid < 32) {
            double v = (tid < 8) ? ws[tid] : 0.0;
#pragma unroll
            for (int o = 4; o > 0; o >>= 1) v += __shfl_down_sync(0xffffffffu, v, o);
            if (tid == 0) { out[0] = (float)v; g_count = 0; }
        }
    }
}

extern "C" void kernel_launch(void* const* d_in, const int* in_sizes, int n_in,
                              void* d_out, int out_size)
{
    const float* flow0 = (const float*)d_in[0];  // (32,2,128,128)
    const float* flow1 = (const float*)d_in[1];  // (32,2,256,256)
    if (n_in >= 2 && in_sizes[0] > in_sizes[1]) {
        const float* t = flow0; flow0 = flow1; flow1 = t;
    }
    fused_kernel<<<NBLOCKS, 256>>>(flow0, flow1, (float*)d_out);
}

// round 14
// speedup vs baseline: 1.3545x; 1.3545x over previous
#include <cuda_runtime.h>

// ---- block layout (f^2 first with high parallelism; then long->short main) ----
// [0,256)    f^2 kz5 : 4 blocks per 256x256 image (64 img)
// [256,320)  f^2 kz3 : 1 block per 128x128 image (64 img)
// [320,604)  kz5 main: quad-col: 64 img x 63 quads x 18 chunks (R=14) = 72576 thr -> 284 blocks
// [604,746)  kz3 main: pair-col: 64 img x 63 pairs x 9 chunks (R=14) = 36288 thr -> 142 blocks
#define B5F        256
#define B3F        64
#define T5_THREADS 72576
#define B5M        284
#define T3_THREADS 36288
#define B3M        142
#define NBLOCKS    (B5F + B3F + B5M + B3M)   // 746

__device__ double g_part[NBLOCKS];
__device__ int    g_count;

typedef unsigned long long u64;

__device__ __forceinline__ u64 pack2(float lo, float hi) {
    u64 r; asm("mov.b64 %0, {%1,%2};" : "=l"(r) : "f"(lo), "f"(hi)); return r;
}
__device__ __forceinline__ u64 fma2(u64 a, u64 b, u64 c) {
    u64 d; asm("fma.rn.f32x2 %0, %1, %2, %3;" : "=l"(d) : "l"(a), "l"(b), "l"(c)); return d;
}
__device__ __forceinline__ u64 add2(u64 a, u64 b) {
    u64 d; asm("add.rn.f32x2 %0, %1, %2;" : "=l"(d) : "l"(a), "l"(b)); return d;
}
__device__ __forceinline__ u64 mul2(u64 a, u64 b) {
    u64 d; asm("mul.rn.f32x2 %0, %1, %2;" : "=l"(d) : "l"(a), "l"(b)); return d;
}
__device__ __forceinline__ void unpack2(u64 v, float& lo, float& hi) {
    asm("mov.b64 {%0,%1}, %2;" : "=f"(lo), "=f"(hi) : "l"(v));
}
__device__ __forceinline__ float lo2(u64 v){ float a,b; unpack2(v,a,b); return a; }
__device__ __forceinline__ float hi2(u64 v){ float a,b; unpack2(v,a,b); return b; }

// ---- kz5 main: 4 output cols (2 pairs) x 14 rows, prefetch + incremental S0/Sc ----
__device__ __forceinline__ float work5(const float* __restrict__ f1, int t)
{
    if (t >= T5_THREADS) return 0.f;
    const int img   = t / 1134;          // 63*18
    int rem         = t - img * 1134;
    const int chunk = rem / 63;
    const int quad  = rem - chunk * 63;
    const float* __restrict__ p = f1 + (size_t)img * 65536
                                + (size_t)(chunk * 14) * 256 + quad * 4;

    const u64 two2  = pack2(2.f, 2.f);
    const u64 neg12 = pack2(-1.f, -1.f);

    u64 r0a[5], rca[5], r0b[5], rcb[5];

#define HQ(F0, F1, s0a, sca, s0b, scb)                                        \
    {                                                                         \
        u64 A = pack2((F0).x, (F0).y);                                        \
        u64 B = pack2((F0).z, (F0).w);                                        \
        u64 C = pack2((F1).x, (F1).y);                                        \
        u64 D = pack2((F1).z, (F1).w);                                        \
        u64 pk1 = pack2((F0).y, (F0).z);                                      \
        u64 pk3 = pack2((F0).w, (F1).x);                                      \
        u64 pk5 = pack2((F1).y, (F1).z);                                      \
        s0a = add2(add2(A, pk1), add2(B, pk3)); s0a = add2(s0a, C);           \
        { u64 d1 = fma2(neg12, pk1, pk3);                                     \
          u64 d2 = fma2(neg12, A, C);                                         \
          sca = fma2(two2, d2, d1); }                                         \
        s0b = add2(add2(B, pk3), add2(C, pk5)); s0b = add2(s0b, D);           \
        { u64 d1 = fma2(neg12, pk3, pk5);                                     \
          u64 d2 = fma2(neg12, B, D);                                         \
          scb = fma2(two2, d2, d1); }                                         \
    }

#pragma unroll
    for (int w = 0; w < 4; w++) {
        float4 F0 = *reinterpret_cast<const float4*>(p);
        float4 F1 = *reinterpret_cast<const float4*>(p + 4);
        HQ(F0, F1, r0a[w], rca[w], r0b[w], rcb[w]);
        p += 256;
    }
    u64 S0pa = add2(add2(r0a[0], r0a[1]), add2(r0a[2], r0a[3]));
    u64 Scpa = add2(add2(rca[0], rca[1]), add2(rca[2], rca[3]));
    u64 S0pb = add2(add2(r0b[0], r0b[1]), add2(r0b[2], r0b[3]));
    u64 Scpb = add2(add2(rcb[0], rcb[1]), add2(rcb[2], rcb[3]));

    float4 A0 = *reinterpret_cast<const float4*>(p);
    float4 A1 = *reinterpret_cast<const float4*>(p + 4);
    p += 256;

    u64 accAa = 0ull, accBa = 0ull, accAb = 0ull, accBb = 0ull;
#pragma unroll
    for (int i = 0; i < 14; i++) {
        float4 N0, N1;
        if (i < 13) {
            N0 = *reinterpret_cast<const float4*>(p);
            N1 = *reinterpret_cast<const float4*>(p + 4);
            p += 256;
        }
        const int sl = (i + 4) % 5;
        HQ(A0, A1, r0a[sl], rca[sl], r0b[sl], rcb[sl]);

        const int a0 = i % 5, a1 = (i + 1) % 5, a3 = (i + 3) % 5;
        {
            u64 S0 = add2(S0pa, r0a[sl]);
            u64 Sc = add2(Scpa, rca[sl]);
            u64 d1 = fma2(neg12, r0a[a1], r0a[a3]);
            u64 d2 = fma2(neg12, r0a[a0], r0a[sl]);
            u64 Sr = fma2(two2, d2, d1);
            accAa = fma2(S0, S0, accAa);
            accBa = fma2(Sr, Sr, accBa);
            accBa = fma2(Sc, Sc, accBa);
            S0pa = fma2(neg12, r0a[a0], S0);
            Scpa = fma2(neg12, rca[a0], Sc);
        }
        {
            u64 S0 = add2(S0pb, r0b[sl]);
            u64 Sc = add2(Scpb, rcb[sl]);
            u64 d1 = fma2(neg12, r0b[a1], r0b[a3]);
            u64 d2 = fma2(neg12, r0b[a0], r0b[sl]);
            u64 Sr = fma2(two2, d2, d1);
            accAb = fma2(S0, S0, accAb);
            accBb = fma2(Sr, Sr, accBb);
            accBb = fma2(Sc, Sc, accBb);
            S0pb = fma2(neg12, r0b[a0], S0);
            Scpb = fma2(neg12, rcb[a0], Sc);
        }
        A0 = N0; A1 = N1;
    }
#undef HQ
    u64 accA = add2(accAa, accAb);
    u64 accB = add2(accBa, accBb);
    float aL, aH, bL, bH;
    unpack2(accA, aL, aH); unpack2(accB, bL, bH);
    return (1.f/25.f) * (aL + aH) + (12.f/(25.f*24.f)) * (bL + bH);
}

// ---- kz3 main: 2 cols x 14 rows ----
__device__ __forceinline__ void hstats3r(u64 A, u64 B, u64 neg12, u64& o0, u64& oc)
{
    u64 pk1 = pack2(hi2(A), lo2(B));
    o0 = add2(add2(A, pk1), B);
    oc = fma2(neg12, A, B);
}
__device__ __forceinline__ float work3(const float* __restrict__ f0, int t)
{
    const int img   = t / 567;           // 63*9
    int rem         = t - img * 567;
    const int chunk = rem / 63;
    const int cg    = rem - chunk * 63;
    const float* __restrict__ p = f0 + (size_t)img * 16384
                                + (size_t)(chunk * 14) * 128 + cg * 2;

    const u64 neg12 = pack2(-1.f, -1.f);

    u64 r0[3], rc[3];
#pragma unroll
    for (int w = 0; w < 2; w++) {
        u64 A = *reinterpret_cast<const u64*>(p);
        u64 B = *reinterpret_cast<const u64*>(p + 2);
        hstats3r(A, B, neg12, r0[w], rc[w]);
        p += 128;
    }
    u64 S0p = add2(r0[0], r0[1]);
    u64 Scp = add2(rc[0], rc[1]);

    u64 A = *reinterpret_cast<const u64*>(p);
    u64 B = *reinterpret_cast<const u64*>(p + 2);
    p += 128;

    u64 accA = 0ull, accB = 0ull;
#pragma unroll
    for (int i = 0; i < 14; i++) {
        u64 nA, nB;
        if (i < 13) {
            nA = *reinterpret_cast<const u64*>(p);
            nB = *reinterpret_cast<const u64*>(p + 2);
            p += 128;
        }
        const int sl = (i + 2) % 3, a0 = i % 3;
        hstats3r(A, B, neg12, r0[sl], rc[sl]);

        u64 S0 = add2(S0p, r0[sl]);
        u64 Sc = add2(Scp, rc[sl]);
        u64 Sr = fma2(neg12, r0[a0], r0[sl]);
        accA = fma2(S0, S0, accA);
        accB = fma2(Sr, Sr, accB);
        accB = fma2(Sc, Sc, accB);
        S0p = fma2(neg12, r0[a0], S0);
        Scp = fma2(neg12, rc[a0], Sc);
        A = nA; B = nB;
    }
    float aL, aH, bL, bH;
    unpack2(accA, aL, aH); unpack2(accB, bL, bH);
    return (1.f/9.f) * (aL + aH) + (12.f/(9.f*8.f)) * (bL + bH);
}

// ---- f^2 weighted pass, kz5: 4 blocks per image (part = 32 k-steps) ----
__device__ __forceinline__ float frow5p(const float* __restrict__ f1, int img,
                                        int part, int tid)
{
    const u64* __restrict__ q = reinterpret_cast<const u64*>(f1 + (size_t)img * 65536);
    const int x0 = 2 * (tid & 127);
    const float wx0 = (float)min(min(x0 + 1, 256 - x0), 5);
    const float wx1 = (float)min(min(x0 + 2, 255 - x0), 5);
    const u64 wx2 = pack2(wx0, wx1);
    const int r0 = tid >> 7;
    const int k0 = part * 32;

    u64 acc = 0ull;
#pragma unroll 8
    for (int kk = 0; kk < 32; kk++) {
        const int k = k0 + kk;
        u64 F = q[tid + (k << 8)];
        const int row = r0 + 2 * k;
        const float wy = (float)min(min(row + 1, 256 - row), 5);
        u64 w = mul2(wx2, pack2(wy, wy));
        acc = fma2(F, mul2(F, w), acc);
    }
    float aL, aH;
    unpack2(acc, aL, aH);
    return aL + aH;
}

// ---- f^2 weighted pass, kz3: 1 block per image ----
__device__ __forceinline__ float frow3img(const float* __restrict__ f0, int img, int tid)
{
    const u64* __restrict__ q = reinterpret_cast<const u64*>(f0 + (size_t)img * 16384);
    const int x0 = 2 * (tid & 63);
    const float wx0 = (float)min(min(x0 + 1, 128 - x0), 3);
    const float wx1 = (float)min(min(x0 + 2, 127 - x0), 3);
    const u64 wx2 = pack2(wx0, wx1);
    const int r0 = tid >> 6;

    u64 acc = 0ull;
#pragma unroll 8
    for (int k = 0; k < 32; k++) {
        u64 F = q[tid + (k << 8)];
        const int row = r0 + 4 * k;
        const float wy = (float)min(min(row + 1, 128 - row), 3);
        u64 w = mul2(wx2, pack2(wy, wy));
        acc = fma2(F, mul2(F, w), acc);
    }
    float aL, aH;
    unpack2(acc, aL, aH);
    return aL + aH;
}

__global__ void __launch_bounds__(256, 3) fused_kernel(const float* __restrict__ f0,
                                                       const float* __restrict__ f1,
                                                       float* __restrict__ out)
{
    const int tid = threadIdx.x;
    const int b   = blockIdx.x;
    float acc = 0.f;
    double scale;

    const double sc5 = 1.0 / (32.0 * 252.0 * 252.0);
    const double sc3 = 1.0 / (32.0 * 126.0 * 126.0);

    if (b < B5F) {                                     // f^2 kz5 (positive)
        acc = frow5p(f1, b >> 2, b & 3, tid);
        scale = sc5;
    } else if (b < B5F + B3F) {                        // f^2 kz3 (positive)
        acc = frow3img(f0, b - B5F, tid);
        scale = sc3;
    } else if (b < B5F + B3F + B5M) {                  // kz5 main (negative)
        acc = work5(f1, (b - B5F - B3F) * 256 + tid);
        scale = -sc5;
    } else {                                           // kz3 main (negative)
        const int t = (b - B5F - B3F - B5M) * 256 + tid;
        if (t < T3_THREADS) acc = work3(f0, t);
        scale = -sc3;
    }

#pragma unroll
    for (int o = 16; o > 0; o >>= 1) acc += __shfl_down_sync(0xffffffffu, acc, o);
    __shared__ float wsum[8];
    __shared__ bool  lastflag;
    if ((tid & 31) == 0) wsum[tid >> 5] = acc;
    __syncthreads();
    if (tid < 32) {
        float v = (tid < 8) ? wsum[tid] : 0.f;
#pragma unroll
        for (int o = 4; o > 0; o >>= 1) v += __shfl_down_sync(0xffffffffu, v, o);
        if (tid == 0) {
            g_part[b] = (double)v * scale;
            __threadfence();
            int done = atomicAdd(&g_count, 1);
            lastflag = (done == NBLOCKS - 1);
        }
    }
    __syncthreads();

    if (lastflag) {
        __threadfence();
        double s = 0.0;
        for (int i = tid; i < NBLOCKS; i += 256) s += g_part[i];
#pragma unroll
        for (int o = 16; o > 0; o >>= 1) s += __shfl_down_sync(0xffffffffu, s, o);
        __shared__ double ws[8];
        if ((tid & 31) == 0) ws[tid >> 5] = s;
        __syncthreads();
        if (tid < 32) {
            double v = (tid < 8) ? ws[tid] : 0.0;
#pragma unroll
            for (int o = 4; o > 0; o >>= 1) v += __shfl_down_sync(0xffffffffu, v, o);
            if (tid == 0) { out[0] = (float)v; g_count = 0; }
        }
    }
}

extern "C" void kernel_launch(void* const* d_in, const int* in_sizes, int n_in,
                              void* d_out, int out_size)
{
    const float* flow0 = (const float*)d_in[0];  // (32,2,128,128)
    const float* flow1 = (const float*)d_in[1];  // (32,2,256,256)
    if (n_in >= 2 && in_sizes[0] > in_sizes[1]) {
        const float* t = flow0; flow0 = flow1; flow1 = t;
    }
    fused_kernel<<<NBLOCKS, 256>>>(flow0, flow1, (float*)d_out);
}

// round 15
// speedup vs baseline: 1.8150x; 1.3400x over previous
#include <cuda_runtime.h>

// ---- block layout (R11 layout, kz5 main retiled to R=18 exact) ----
// [0,64)    f^2 kz5 : 1 block per 256x256 image
// [64,96)   f^2 kz3 : 1 block per 2 128x128 images
// [96,537)  kz5 main: pair-col: 64 img x 126 pairs x 14 chunks (R=18) = 112896 thr = 441 blocks
// [537,679) kz3 main: pair-col: 64 img x 63 pairs x 9 chunks (R=14) = 36288 thr = 142 blocks
#define B5F        64
#define B3F        32
#define B5M        441
#define T3_THREADS 36288
#define B3M        142
#define NBLOCKS    (B5F + B3F + B5M + B3M)   // 679

__device__ double g_part[NBLOCKS];
__device__ int    g_count;

typedef unsigned long long u64;

__device__ __forceinline__ u64 pack2(float lo, float hi) {
    u64 r; asm("mov.b64 %0, {%1,%2};" : "=l"(r) : "f"(lo), "f"(hi)); return r;
}
__device__ __forceinline__ u64 fma2(u64 a, u64 b, u64 c) {
    u64 d; asm("fma.rn.f32x2 %0, %1, %2, %3;" : "=l"(d) : "l"(a), "l"(b), "l"(c)); return d;
}
__device__ __forceinline__ u64 add2(u64 a, u64 b) {
    u64 d; asm("add.rn.f32x2 %0, %1, %2;" : "=l"(d) : "l"(a), "l"(b)); return d;
}
__device__ __forceinline__ u64 mul2(u64 a, u64 b) {
    u64 d; asm("mul.rn.f32x2 %0, %1, %2;" : "=l"(d) : "l"(a), "l"(b)); return d;
}
__device__ __forceinline__ void unpack2(u64 v, float& lo, float& hi) {
    asm("mov.b64 {%0,%1}, %2;" : "=f"(lo), "=f"(hi) : "l"(v));
}
__device__ __forceinline__ float lo2(u64 v){ float a,b; unpack2(v,a,b); return a; }
__device__ __forceinline__ float hi2(u64 v){ float a,b; unpack2(v,a,b); return b; }

// ---- hstats from pre-loaded raw registers ----
__device__ __forceinline__ void hstats5r(u64 A, u64 B, u64 C,
                                         u64 two2, u64 neg12, u64& o0, u64& oc)
{
    u64 pk1 = pack2(hi2(A), lo2(B));               // (f1,f2)
    u64 pk3 = pack2(hi2(B), lo2(C));               // (f3,f4)
    u64 s0 = add2(add2(A, pk1), add2(B, pk3));
    o0 = add2(s0, C);
    u64 d1 = fma2(neg12, pk1, pk3);
    u64 d2 = fma2(neg12, A, C);
    oc = fma2(two2, d2, d1);
}
__device__ __forceinline__ void hstats3r(u64 A, u64 B, u64 neg12, u64& o0, u64& oc)
{
    u64 pk1 = pack2(hi2(A), lo2(B));
    o0 = add2(add2(A, pk1), B);
    oc = fma2(neg12, A, B);
}

// ---- kz5 main: 2 cols x 18 rows, DISTANCE-2 prefetch + incremental S0/Sc ----
__device__ __forceinline__ float work5(const float* __restrict__ f1, int t)
{
    const int img   = t / 1764;          // 126*14
    int rem         = t - img * 1764;
    const int chunk = rem / 126;
    const int cg    = rem - chunk * 126;
    const float* __restrict__ p = f1 + (size_t)img * 65536
                                + (size_t)(chunk * 18) * 256 + cg * 2;

    const u64 two2  = pack2(2.f, 2.f);
    const u64 neg12 = pack2(-1.f, -1.f);

    u64 r0[5], rc[5];
#pragma unroll
    for (int w = 0; w < 4; w++) {                 // rows 0..3
        u64 A = *reinterpret_cast<const u64*>(p);
        u64 B = *reinterpret_cast<const u64*>(p + 2);
        u64 C = *reinterpret_cast<const u64*>(p + 4);
        hstats5r(A, B, C, two2, neg12, r0[w], rc[w]);
        p += 256;
    }
    u64 S0p = add2(add2(r0[0], r0[1]), add2(r0[2], r0[3]));
    u64 Scp = add2(add2(rc[0], rc[1]), add2(rc[2], rc[3]));

    // prefetch rows 4 and 5 into double buffer
    u64 bA[2], bB[2], bC[2];
#pragma unroll
    for (int w = 0; w < 2; w++) {
        bA[w] = *reinterpret_cast<const u64*>(p);
        bB[w] = *reinterpret_cast<const u64*>(p + 2);
        bC[w] = *reinterpret_cast<const u64*>(p + 4);
        p += 256;
    }

    u64 accA = 0ull, accB = 0ull;
#pragma unroll
    for (int i = 0; i < 18; i++) {
        const int bi = i & 1;
        u64 A = bA[bi], B = bB[bi], C = bC[bi];   // row i+4
        if (i < 16) {                              // load row i+6 -> freed slot
            bA[bi] = *reinterpret_cast<const u64*>(p);
            bB[bi] = *reinterpret_cast<const u64*>(p + 2);
            bC[bi] = *reinterpret_cast<const u64*>(p + 4);
            p += 256;
        }
        const int sl = (i + 4) % 5;
        hstats5r(A, B, C, two2, neg12, r0[sl], rc[sl]);

        u64 S0 = add2(S0p, r0[sl]);
        u64 Sc = add2(Scp, rc[sl]);
        const int a0 = i % 5, a1 = (i + 1) % 5, a3 = (i + 3) % 5;
        u64 d1 = fma2(neg12, r0[a1], r0[a3]);
        u64 d2 = fma2(neg12, r0[a0], r0[sl]);
        u64 Sr = fma2(two2, d2, d1);
        accA = fma2(S0, S0, accA);
        accB = fma2(Sr, Sr, accB);
        accB = fma2(Sc, Sc, accB);
        S0p = fma2(neg12, r0[a0], S0);
        Scp = fma2(neg12, rc[a0], Sc);
    }
    float aL, aH, bL, bH;
    unpack2(accA, aL, aH); unpack2(accB, bL, bH);
    return (1.f/25.f) * (aL + aH) + (12.f/(25.f*24.f)) * (bL + bH);
}

// ---- kz3 main: 2 cols x 14 rows, DISTANCE-2 prefetch ----
__device__ __forceinline__ float work3(const float* __restrict__ f0, int t)
{
    const int img   = t / 567;           // 63*9
    int rem         = t - img * 567;
    const int chunk = rem / 63;
    const int cg    = rem - chunk * 63;
    const float* __restrict__ p = f0 + (size_t)img * 16384
                                + (size_t)(chunk * 14) * 128 + cg * 2;

    const u64 neg12 = pack2(-1.f, -1.f);

    u64 r0[3], rc[3];
#pragma unroll
    for (int w = 0; w < 2; w++) {                 // rows 0..1
        u64 A = *reinterpret_cast<const u64*>(p);
        u64 B = *reinterpret_cast<const u64*>(p + 2);
        hstats3r(A, B, neg12, r0[w], rc[w]);
        p += 128;
    }
    u64 S0p = add2(r0[0], r0[1]);
    u64 Scp = add2(rc[0], rc[1]);

    u64 bA[2], bB[2];
#pragma unroll
    for (int w = 0; w < 2; w++) {                 // rows 2,3
        bA[w] = *reinterpret_cast<const u64*>(p);
        bB[w] = *reinterpret_cast<const u64*>(p + 2);
        p += 128;
    }

    u64 accA = 0ull, accB = 0ull;
#pragma unroll
    for (int i = 0; i < 14; i++) {
        const int bi = i & 1;
        u64 A = bA[bi], B = bB[bi];               // row i+2
        if (i < 12) {                              // load row i+4
            bA[bi] = *reinterpret_cast<const u64*>(p);
            bB[bi] = *reinterpret_cast<const u64*>(p + 2);
            p += 128;
        }
        const int sl = (i + 2) % 3, a0 = i % 3;
        hstats3r(A, B, neg12, r0[sl], rc[sl]);

        u64 S0 = add2(S0p, r0[sl]);
        u64 Sc = add2(Scp, rc[sl]);
        u64 Sr = fma2(neg12, r0[a0], r0[sl]);
        accA = fma2(S0, S0, accA);
        accB = fma2(Sr, Sr, accB);
        accB = fma2(Sc, Sc, accB);
        S0p = fma2(neg12, r0[a0], S0);
        Scp = fma2(neg12, rc[a0], Sc);
    }
    float aL, aH, bL, bH;
    unpack2(accA, aL, aH); unpack2(accB, bL, bH);
    return (1.f/9.f) * (aL + aH) + (12.f/(9.f*8.f)) * (bL + bH);
}

// ---- f^2 weighted pass, kz5: 1 block per image ----
__device__ __forceinline__ float frow5(const float* __restrict__ f1, int img, int tid)
{
    const u64* __restrict__ q = reinterpret_cast<const u64*>(f1 + (size_t)img * 65536);
    const int x0 = 2 * (tid & 127);
    const float wx0 = (float)min(min(x0 + 1, 256 - x0), 5);
    const float wx1 = (float)min(min(x0 + 2, 255 - x0), 5);
    const u64 wx2 = pack2(wx0, wx1);

    u64 acc5 = 0ull;
#pragma unroll 8
    for (int k = 2; k < 126; k++) {
        u64 F = q[tid + (k << 8)];
        acc5 = fma2(F, mul2(F, wx2), acc5);
    }
    u64 acce = 0ull;
    const int r0 = tid >> 7;
#pragma unroll
    for (int e = 0; e < 4; e++) {
        const int k = (e < 2) ? e : (124 + e);
        const int row = r0 + 2 * k;
        const float wy = (float)min(min(row + 1, 256 - row), 5);
        u64 F = q[tid + (k << 8)];
        acce = fma2(F, mul2(F, mul2(wx2, pack2(wy, wy))), acce);
    }
    float aL, aH, eL, eH;
    unpack2(acc5, aL, aH); unpack2(acce, eL, eH);
    return 5.f * (aL + aH) + (eL + eH);
}

// ---- f^2 weighted pass, kz3: per image ----
__device__ __forceinline__ float frow3img(const float* __restrict__ f0, int img, int tid)
{
    const u64* __restrict__ q = reinterpret_cast<const u64*>(f0 + (size_t)img * 16384);
    const int x0 = 2 * (tid & 63);
    const float wx0 = (float)min(min(x0 + 1, 128 - x0), 3);
    const float wx1 = (float)min(min(x0 + 2, 127 - x0), 3);
    const u64 wx2 = pack2(wx0, wx1);

    u64 acc3 = 0ull;
#pragma unroll 8
    for (int k = 1; k < 31; k++) {
        u64 F = q[tid + (k << 8)];
        acc3 = fma2(F, mul2(F, wx2), acc3);
    }
    u64 acce = 0ull;
    const int r0 = tid >> 6;
#pragma unroll
    for (int e = 0; e < 2; e++) {
        const int k = e * 31;
        const int row = r0 + 4 * k;
        const float wy = (float)min(min(row + 1, 128 - row), 3);
        u64 F = q[tid + (k << 8)];
        acce = fma2(F, mul2(F, mul2(wx2, pack2(wy, wy))), acce);
    }
    float aL, aH, eL, eH;
    unpack2(acc3, aL, aH); unpack2(acce, eL, eH);
    return 3.f * (aL + aH) + (eL + eH);
}

__global__ void __launch_bounds__(256, 3) fused_kernel(const float* __restrict__ f0,
                                                       const float* __restrict__ f1,
                                                       float* __restrict__ out)
{
    const int tid = threadIdx.x;
    const int b   = blockIdx.x;
    float acc = 0.f;
    double scale;

    const double sc5 = 1.0 / (32.0 * 252.0 * 252.0);
    const double sc3 = 1.0 / (32.0 * 126.0 * 126.0);

    if (b < B5F) {                                     // f^2 kz5 (positive)
        acc = frow5(f1, b, tid);
        scale = sc5;
    } else if (b < B5F + B3F) {                        // f^2 kz3 (positive), 2 imgs
        const int i0 = (b - B5F) * 2;
        acc = frow3img(f0, i0, tid) + frow3img(f0, i0 + 1, tid);
        scale = sc3;
    } else if (b < B5F + B3F + B5M) {                  // kz5 main (negative)
        acc = work5(f1, (b - B5F - B3F) * 256 + tid);  // exact fit
        scale = -sc5;
    } else {                                           // kz3 main (negative)
        const int t = (b - B5F - B3F - B5M) * 256 + tid;
        if (t < T3_THREADS) acc = work3(f0, t);
        scale = -sc3;
    }

#pragma unroll
    for (int o = 16; o > 0; o >>= 1) acc += __shfl_down_sync(0xffffffffu, acc, o);
    __shared__ float wsum[8];
    __shared__ bool  lastflag;
    if ((tid & 31) == 0) wsum[tid >> 5] = acc;
    __syncthreads();
    if (tid < 32) {
        float v = (tid < 8) ? wsum[tid] : 0.f;
#pragma unroll
        for (int o = 4; o > 0; o >>= 1) v += __shfl_down_sync(0xffffffffu, v, o);
        if (tid == 0) {
            g_part[b] = (double)v * scale;
            __threadfence();
            int done = atomicAdd(&g_count, 1);
            lastflag = (done == NBLOCKS - 1);
        }
    }
    __syncthreads();

    if (lastflag) {
        __threadfence();
        double s = 0.0;
        for (int i = tid; i < NBLOCKS; i += 256) s += g_part[i];
#pragma unroll
        for (int o = 16; o > 0; o >>= 1) s += __shfl_down_sync(0xffffffffu, s, o);
        __shared__ double ws[8];
        if ((tid & 31) == 0) ws[tid >> 5] = s;
        __syncthreads();
        if (tid < 32) {
            double v = (tid < 8) ? ws[tid] : 0.0;
#pragma unroll
            for (int o = 4; o > 0; o >>= 1) v += __shfl_down_sync(0xffffffffu, v, o);
            if (tid == 0) { out[0] = (float)v; g_count = 0; }
        }
    }
}

extern "C" void kernel_launch(void* const* d_in, const int* in_sizes, int n_in,
                              void* d_out, int out_size)
{
    const float* flow0 = (const float*)d_in[0];  // (32,2,128,128)
    const float* flow1 = (const float*)d_in[1];  // (32,2,256,256)
    if (n_in >= 2 && in_sizes[0] > in_sizes[1]) {
        const float* t = flow0; flow0 = flow1; flow1 = t;
    }
    fused_kernel<<<NBLOCKS, 256>>>(flow0, flow1, (float*)d_out);
}